// round 1
// baseline (speedup 1.0000x reference)
#include <cuda_runtime.h>

// Problem dims (fixed by the reference)
#define BB   8
#define TT   1024
#define EE   1024
#define HH   16
#define HS   64

// Scratch: q,k,v and attention output, all in [B, T, H*HS] row-major layout
// (column index = h*HS + d) so every GEMM has a plain row-major epilogue.
__device__ float g_q[BB * TT * EE];
__device__ float g_k[BB * TT * EE];
__device__ float g_v[BB * TT * EE];
__device__ float g_att[BB * TT * EE];

// ---------------------------------------------------------------------------
// Generic SGEMM:  C[M,N] = A[M,K] * W[N,K]^T   (all row-major, K = EE = 1024)
// BM=BN=128, BK=8, 256 threads, 8x8 microtile per thread.
// ---------------------------------------------------------------------------
#define GBM 128
#define GBN 128
#define GBK 8
#define GTM 8
#define GTN 8

__global__ __launch_bounds__(256)
void gemm_abt_kernel(const float* __restrict__ A,
                     const float* __restrict__ W,
                     float* __restrict__ C,
                     int M, int N, int K)
{
    __shared__ float As[GBK][GBM];
    __shared__ float Ws[GBK][GBN];

    const int tid = threadIdx.x;
    const int bm  = blockIdx.y * GBM;
    const int bn  = blockIdx.x * GBN;
    const int tx  = tid & 15;   // 16 columns of threads
    const int ty  = tid >> 4;   // 16 rows of threads

    // Loader mapping: 256 threads load 128 rows x 8 cols (one float4 each)
    const int lrow = tid >> 1;          // 0..127
    const int lcol = (tid & 1) * 4;     // 0 or 4

    float acc[GTM][GTN];
#pragma unroll
    for (int i = 0; i < GTM; i++)
#pragma unroll
        for (int j = 0; j < GTN; j++) acc[i][j] = 0.0f;

    const float* Aptr = A + (long)(bm + lrow) * K + lcol;
    const float* Wptr = W + (long)(bn + lrow) * K + lcol;

    for (int k0 = 0; k0 < K; k0 += GBK) {
        float4 a4 = *(const float4*)(Aptr + k0);
        float4 w4 = *(const float4*)(Wptr + k0);
        As[lcol + 0][lrow] = a4.x;
        As[lcol + 1][lrow] = a4.y;
        As[lcol + 2][lrow] = a4.z;
        As[lcol + 3][lrow] = a4.w;
        Ws[lcol + 0][lrow] = w4.x;
        Ws[lcol + 1][lrow] = w4.y;
        Ws[lcol + 2][lrow] = w4.z;
        Ws[lcol + 3][lrow] = w4.w;
        __syncthreads();

#pragma unroll
        for (int kk = 0; kk < GBK; kk++) {
            float fa[GTM], fb[GTN];
            float4 fa0 = *(const float4*)&As[kk][ty * GTM + 0];
            float4 fa1 = *(const float4*)&As[kk][ty * GTM + 4];
            float4 fb0 = *(const float4*)&Ws[kk][tx * GTN + 0];
            float4 fb1 = *(const float4*)&Ws[kk][tx * GTN + 4];
            fa[0]=fa0.x; fa[1]=fa0.y; fa[2]=fa0.z; fa[3]=fa0.w;
            fa[4]=fa1.x; fa[5]=fa1.y; fa[6]=fa1.z; fa[7]=fa1.w;
            fb[0]=fb0.x; fb[1]=fb0.y; fb[2]=fb0.z; fb[3]=fb0.w;
            fb[4]=fb1.x; fb[5]=fb1.y; fb[6]=fb1.z; fb[7]=fb1.w;
#pragma unroll
            for (int i = 0; i < GTM; i++)
#pragma unroll
                for (int j = 0; j < GTN; j++)
                    acc[i][j] = fmaf(fa[i], fb[j], acc[i][j]);
        }
        __syncthreads();
    }

    // Epilogue: plain row-major store (M, N are multiples of tile dims here)
#pragma unroll
    for (int i = 0; i < GTM; i++) {
        float* crow = C + (long)(bm + ty * GTM + i) * N + bn + tx * GTN;
#pragma unroll
        for (int j = 0; j < GTN; j += 4) {
            float4 v4;
            v4.x = acc[i][j + 0];
            v4.y = acc[i][j + 1];
            v4.z = acc[i][j + 2];
            v4.w = acc[i][j + 3];
            *(float4*)(crow + j) = v4;
        }
    }
}

// ---------------------------------------------------------------------------
// Causal flash attention, fp32.
// One thread per query row; 128 query rows per block; 64-key shared tiles.
// grid = (T/128, H, B).
// ---------------------------------------------------------------------------
#define AQ 128   // query rows per block == threads per block
#define AK 64    // key tile

__global__ __launch_bounds__(AQ)
void attn_kernel(const float* __restrict__ gq,
                 const float* __restrict__ gk,
                 const float* __restrict__ gv,
                 float* __restrict__ gatt)
{
    __shared__ float Ksh[AK][HS];
    __shared__ float Vsh[AK][HS];

    const int b = blockIdx.z;
    const int h = blockIdx.y;
    const int t = blockIdx.x * AQ + threadIdx.x;

    const long rowbase = (long)(b * TT + t) * EE + h * HS;

    float q[HS];
#pragma unroll
    for (int d = 0; d < HS; d += 4) {
        float4 q4 = *(const float4*)(gq + rowbase + d);
        q[d+0]=q4.x; q[d+1]=q4.y; q[d+2]=q4.z; q[d+3]=q4.w;
    }

    float o[HS];
#pragma unroll
    for (int d = 0; d < HS; d++) o[d] = 0.0f;
    float m = -INFINITY;
    float l = 0.0f;

    const int kend = blockIdx.x * AQ + AQ;  // max key index + 1 needed by this block

    for (int j0 = 0; j0 < kend; j0 += AK) {
        // Cooperative tile load: 64x64 floats each for K and V
        for (int i = threadIdx.x; i < AK * HS / 4; i += AQ) {
            int j = (i * 4) / HS;
            int d = (i * 4) % HS;
            long src = (long)(b * TT + j0 + j) * EE + h * HS + d;
            *(float4*)&Ksh[j][d] = *(const float4*)(gk + src);
            *(float4*)&Vsh[j][d] = *(const float4*)(gv + src);
        }
        __syncthreads();

#pragma unroll 1
        for (int c = 0; c < AK; c += 16) {
            if (j0 + c > t) break;  // whole chunk masked (keys increase)

            float s[16];
#pragma unroll
            for (int jj = 0; jj < 16; jj++) {
                float acc = 0.0f;
#pragma unroll
                for (int d = 0; d < HS; d++)
                    acc = fmaf(q[d], Ksh[c + jj][d], acc);
                s[jj] = (j0 + c + jj <= t) ? acc * 0.125f : -INFINITY;  // 1/sqrt(64)
            }

            float mc = s[0];
#pragma unroll
            for (int jj = 1; jj < 16; jj++) mc = fmaxf(mc, s[jj]);
            float mn = fmaxf(m, mc);          // finite: first key of chunk is valid
            float scale = __expf(m - mn);     // 0 when m == -inf
            l *= scale;
#pragma unroll
            for (int d = 0; d < HS; d++) o[d] *= scale;

#pragma unroll
            for (int jj = 0; jj < 16; jj++) {
                float p = __expf(s[jj] - mn);
                l += p;
#pragma unroll
                for (int d = 0; d < HS; d++)
                    o[d] = fmaf(p, Vsh[c + jj][d], o[d]);
            }
            m = mn;
        }
        __syncthreads();
    }

    const float inv = 1.0f / l;  // l > 0: diagonal key always valid
    float* op = gatt + rowbase;
#pragma unroll
    for (int d = 0; d < HS; d += 4) {
        float4 v4;
        v4.x = o[d+0] * inv;
        v4.y = o[d+1] * inv;
        v4.z = o[d+2] * inv;
        v4.w = o[d+3] * inv;
        *(float4*)(op + d) = v4;
    }
}

// ---------------------------------------------------------------------------
// Launch
// Inputs (metadata order): x [B,T,E] f32, Wk [H,HS,E] f32, Wq, Wv,
//                          Wproj [E,E] f32, i (int, ignored)
// Output: [B,T,E] f32
// ---------------------------------------------------------------------------
extern "C" void kernel_launch(void* const* d_in, const int* in_sizes, int n_in,
                              void* d_out, int out_size)
{
    (void)in_sizes; (void)n_in; (void)out_size;
    const float* x     = (const float*)d_in[0];
    const float* Wk    = (const float*)d_in[1];
    const float* Wq    = (const float*)d_in[2];
    const float* Wv    = (const float*)d_in[3];
    const float* Wproj = (const float*)d_in[4];
    float* out = (float*)d_out;

    float *q_ptr, *k_ptr, *v_ptr, *att_ptr;
    cudaGetSymbolAddress((void**)&q_ptr,   g_q);
    cudaGetSymbolAddress((void**)&k_ptr,   g_k);
    cudaGetSymbolAddress((void**)&v_ptr,   g_v);
    cudaGetSymbolAddress((void**)&att_ptr, g_att);

    const int M = BB * TT;   // 8192
    const int N = EE;        // 1024
    const int K = EE;        // 1024

    dim3 gblk(256);
    dim3 ggrid(N / GBN, M / GBM);  // (8, 64)

    // QKV projections (Wk/Wq/Wv rows are [h*HS+d, E] flattened -> plain A*W^T)
    gemm_abt_kernel<<<ggrid, gblk>>>(x, Wk, k_ptr, M, N, K);
    gemm_abt_kernel<<<ggrid, gblk>>>(x, Wq, q_ptr, M, N, K);
    gemm_abt_kernel<<<ggrid, gblk>>>(x, Wv, v_ptr, M, N, K);

    // Causal attention -> g_att in [B,T,H*HS]
    dim3 agrid(TT / AQ, HH, BB);  // (8, 16, 8)
    attn_kernel<<<agrid, AQ>>>(q_ptr, k_ptr, v_ptr, att_ptr);

    // Output projection: out = att @ Wproj^T
    gemm_abt_kernel<<<ggrid, gblk>>>(att_ptr, Wproj, out, M, N, K);
}

// round 17
// speedup vs baseline: 1.5559x; 1.5559x over previous
#include <cuda_runtime.h>
#include <cuda_bf16.h>
#include <cstdint>

// Problem dims (fixed by the reference)
#define BB   8
#define TT   1024
#define EE   1024
#define HH   16
#define HS   64

// Scratch in [B, T, H*HS] row-major
__device__ float g_q[BB * TT * EE];
__device__ float g_k[BB * TT * EE];
__device__ float g_v[BB * TT * EE];
__device__ float g_att[BB * TT * EE];

// ---------------------------------------------------------------------------
// GEMM via mma.sync.m16n8k16 bf16 (HMMA path — legal on base compute_103,
// unlike tcgen05 which the harness's PTX target rejects).
// bf16x3 precision recovery: x = hi + lo (bf16 each); hi*hi + hi*lo + lo*hi
// in fp32 accumulators. Dropped lo*lo term ~2^-18 relative.
// C[M,N] = A[M,K] * W[N,K]^T, row-major. CTA tile 128x128, BK=16,
// 256 threads = 8 warps in 2(m) x 4(n) grid, warp tile 64x32.
// ---------------------------------------------------------------------------
#define GBM 128
#define GBN 128
#define GBK 16

__device__ __forceinline__ void mma_bf16(float& c0, float& c1, float& c2, float& c3,
                                         uint32_t a0, uint32_t a1, uint32_t a2, uint32_t a3,
                                         uint32_t b0, uint32_t b1)
{
    asm volatile(
        "mma.sync.aligned.m16n8k16.row.col.f32.bf16.bf16.f32 "
        "{%0,%1,%2,%3}, {%4,%5,%6,%7}, {%8,%9}, {%0,%1,%2,%3};"
        : "+f"(c0), "+f"(c1), "+f"(c2), "+f"(c3)
        : "r"(a0), "r"(a1), "r"(a2), "r"(a3), "r"(b0), "r"(b1));
}

// Convert 8 fp32 -> 8 bf16 hi (packed uint4) + 8 bf16 lo (packed uint4)
__device__ __forceinline__ void cvt8_hilo(float4 u, float4 v, uint4& hi, uint4& lo)
{
    float xs[8] = {u.x, u.y, u.z, u.w, v.x, v.y, v.z, v.w};
    uint32_t hb[8], lb[8];
#pragma unroll
    for (int i = 0; i < 8; i++) {
        __nv_bfloat16 h = __float2bfloat16_rn(xs[i]);
        float rem = xs[i] - __bfloat162float(h);
        __nv_bfloat16 l = __float2bfloat16_rn(rem);
        hb[i] = (uint32_t)__bfloat16_as_ushort(h);
        lb[i] = (uint32_t)__bfloat16_as_ushort(l);
    }
    hi.x = hb[0] | (hb[1] << 16);
    hi.y = hb[2] | (hb[3] << 16);
    hi.z = hb[4] | (hb[5] << 16);
    hi.w = hb[6] | (hb[7] << 16);
    lo.x = lb[0] | (lb[1] << 16);
    lo.y = lb[2] | (lb[3] << 16);
    lo.z = lb[4] | (lb[5] << 16);
    lo.w = lb[6] | (lb[7] << 16);
}

__global__ __launch_bounds__(256, 2)
void gemm_bf16x3_kernel(const float* __restrict__ A,
                        const float* __restrict__ W,
                        float* __restrict__ C,
                        int M, int N, int K)
{
    // smem: [2 buffers][4 arrays: Ahi, Alo, Bhi, Blo][128 rows][16 bf16]
    __shared__ __nv_bfloat16 sAhi[2][GBM][GBK];
    __shared__ __nv_bfloat16 sAlo[2][GBM][GBK];
    __shared__ __nv_bfloat16 sBhi[2][GBN][GBK];
    __shared__ __nv_bfloat16 sBlo[2][GBN][GBK];

    const int tid  = threadIdx.x;
    const int wid  = tid >> 5;
    const int lane = tid & 31;
    const int bm   = blockIdx.y * GBM;
    const int bn   = blockIdx.x * GBN;

    const int wm = (wid >> 2) * 64;   // warp m offset (0 or 64)
    const int wn = (wid & 3) * 32;    // warp n offset (0,32,64,96)
    const int g  = lane >> 2;         // group id 0..7
    const int tg = lane & 3;          // thread-in-group 0..3

    // Loader mapping: 256 threads cover 128 rows x 16 cols (8 floats/thread)
    const int lrow = tid >> 1;            // 0..127
    const int lseg = (tid & 1) * 8;       // 0 or 8

    const float* aptr = A + (size_t)(bm + lrow) * K + lseg;
    const float* bptr = W + (size_t)(bn + lrow) * K + lseg;

    float acc[4][4][4];
#pragma unroll
    for (int mi = 0; mi < 4; mi++)
#pragma unroll
        for (int ni = 0; ni < 4; ni++)
#pragma unroll
            for (int r = 0; r < 4; r++) acc[mi][ni][r] = 0.0f;

    // Prologue: load stage 0
    {
        float4 a0 = *(const float4*)(aptr + 0);
        float4 a1 = *(const float4*)(aptr + 4);
        float4 b0 = *(const float4*)(bptr + 0);
        float4 b1 = *(const float4*)(bptr + 4);
        uint4 hi, lo;
        cvt8_hilo(a0, a1, hi, lo);
        *(uint4*)&sAhi[0][lrow][lseg] = hi;
        *(uint4*)&sAlo[0][lrow][lseg] = lo;
        cvt8_hilo(b0, b1, hi, lo);
        *(uint4*)&sBhi[0][lrow][lseg] = hi;
        *(uint4*)&sBlo[0][lrow][lseg] = lo;
    }
    __syncthreads();

    const int nstage = K / GBK;   // 64

    for (int s = 0; s < nstage; s++) {
        const int buf = s & 1;

        // Prefetch next stage into registers (overlaps with compute below)
        float4 pa0, pa1, pb0, pb1;
        if (s < nstage - 1) {
            const int kn = (s + 1) * GBK;
            pa0 = *(const float4*)(aptr + kn + 0);
            pa1 = *(const float4*)(aptr + kn + 4);
            pb0 = *(const float4*)(bptr + kn + 0);
            pb1 = *(const float4*)(bptr + kn + 4);
        }

        // ---- Compute from smem[buf] ----
        const uint32_t* pAhi = (const uint32_t*)&sAhi[buf][0][0];  // row stride 8 u32
        const uint32_t* pAlo = (const uint32_t*)&sAlo[buf][0][0];
        const uint32_t* pBhi = (const uint32_t*)&sBhi[buf][0][0];
        const uint32_t* pBlo = (const uint32_t*)&sBlo[buf][0][0];

        uint32_t ahi[4][4], alo[4][4];
#pragma unroll
        for (int mi = 0; mi < 4; mi++) {
            const int r0 = (wm + mi * 16 + g) * 8;
            const int r1 = (wm + mi * 16 + g + 8) * 8;
            ahi[mi][0] = pAhi[r0 + tg];
            ahi[mi][1] = pAhi[r1 + tg];
            ahi[mi][2] = pAhi[r0 + tg + 4];
            ahi[mi][3] = pAhi[r1 + tg + 4];
            alo[mi][0] = pAlo[r0 + tg];
            alo[mi][1] = pAlo[r1 + tg];
            alo[mi][2] = pAlo[r0 + tg + 4];
            alo[mi][3] = pAlo[r1 + tg + 4];
        }

#pragma unroll
        for (int ni = 0; ni < 4; ni++) {
            const int rb = (wn + ni * 8 + g) * 8;
            const uint32_t bhi0 = pBhi[rb + tg];
            const uint32_t bhi1 = pBhi[rb + tg + 4];
            const uint32_t blo0 = pBlo[rb + tg];
            const uint32_t blo1 = pBlo[rb + tg + 4];
#pragma unroll
            for (int mi = 0; mi < 4; mi++) {
                float* c = acc[mi][ni];
                mma_bf16(c[0], c[1], c[2], c[3],
                         ahi[mi][0], ahi[mi][1], ahi[mi][2], ahi[mi][3], bhi0, bhi1);
                mma_bf16(c[0], c[1], c[2], c[3],
                         ahi[mi][0], ahi[mi][1], ahi[mi][2], ahi[mi][3], blo0, blo1);
                mma_bf16(c[0], c[1], c[2], c[3],
                         alo[mi][0], alo[mi][1], alo[mi][2], alo[mi][3], bhi0, bhi1);
            }
        }

        // ---- Store prefetched stage to the other buffer ----
        if (s < nstage - 1) {
            __syncthreads();   // all warps finished computing stage s
            uint4 hi, lo;
            cvt8_hilo(pa0, pa1, hi, lo);
            *(uint4*)&sAhi[buf ^ 1][lrow][lseg] = hi;
            *(uint4*)&sAlo[buf ^ 1][lrow][lseg] = lo;
            cvt8_hilo(pb0, pb1, hi, lo);
            *(uint4*)&sBhi[buf ^ 1][lrow][lseg] = hi;
            *(uint4*)&sBlo[buf ^ 1][lrow][lseg] = lo;
            __syncthreads();   // stores visible before stage s+1 compute
        }
    }

    // Epilogue: write accumulators (fragment rows g / g+8, cols tg*2, tg*2+1)
#pragma unroll
    for (int mi = 0; mi < 4; mi++) {
#pragma unroll
        for (int ni = 0; ni < 4; ni++) {
            const int row = bm + wm + mi * 16 + g;
            const int col = bn + wn + ni * 8 + tg * 2;
            float* c = acc[mi][ni];
            *(float2*)(C + (size_t)row * N + col)       = make_float2(c[0], c[1]);
            *(float2*)(C + (size_t)(row + 8) * N + col) = make_float2(c[2], c[3]);
        }
    }
}

// ---------------------------------------------------------------------------
// Causal flash attention, fp32, 2 threads per query row (register split).
// Each thread owns 32 of 64 head dims; pair-local shfl completes QK dots.
// Softmax state replicated per pair lane (identical arithmetic).
// grid = (T/64, H, B), block = 128 threads.
// ---------------------------------------------------------------------------
#define AQR 64   // query rows per block
#define ATH 128  // threads per block (2 per row)
#define AK  64   // key tile
#define KST 72   // padded K/V row stride in floats: halves at 0 and 36

__global__ __launch_bounds__(ATH)
void attn2_kernel(const float* __restrict__ gq,
                  const float* __restrict__ gk,
                  const float* __restrict__ gv,
                  float* __restrict__ gatt)
{
    __shared__ float Ksh[AK * KST];
    __shared__ float Vsh[AK * KST];

    const int b = blockIdx.z;
    const int h = blockIdx.y;
    const int row  = blockIdx.x * AQR + (threadIdx.x >> 1);
    const int half = threadIdx.x & 1;
    const unsigned pmask = 0x3u << ((threadIdx.x & 31) & 30);  // lane-pair mask

    const long rowbase = (long)(b * TT + row) * EE + h * HS;
    const int dlog  = half * 32;  // logical head-dim offset
    const int dphys = half * 36;  // physical offset within padded SMEM row

    float q[32];
#pragma unroll
    for (int d = 0; d < 32; d += 4) {
        float4 q4 = *(const float4*)(gq + rowbase + dlog + d);
        q[d+0]=q4.x; q[d+1]=q4.y; q[d+2]=q4.z; q[d+3]=q4.w;
    }

    float o[32];
#pragma unroll
    for (int d = 0; d < 32; d++) o[d] = 0.0f;
    float m = -INFINITY;
    float l = 0.0f;

    const int kend = blockIdx.x * AQR + AQR;

    for (int j0 = 0; j0 < kend; j0 += AK) {
        for (int i = threadIdx.x; i < AK * 16; i += ATH) {
            const int j  = i >> 4;
            const int c4 = (i & 15) * 4;
            const int ph = (c4 < 32) ? c4 : c4 + 4;
            const long src = (long)(b * TT + j0 + j) * EE + h * HS + c4;
            *(float4*)&Ksh[j * KST + ph] = *(const float4*)(gk + src);
            *(float4*)&Vsh[j * KST + ph] = *(const float4*)(gv + src);
        }
        __syncthreads();

#pragma unroll 1
        for (int c = 0; c < AK; c += 16) {
            if (j0 + c > row) break;   // pair-uniform

            float s[16];
#pragma unroll
            for (int jj = 0; jj < 16; jj++) {
                const float* kr = &Ksh[(c + jj) * KST + dphys];
                float acc = 0.0f;
#pragma unroll
                for (int d = 0; d < 32; d++)
                    acc = fmaf(q[d], kr[d], acc);
                acc += __shfl_xor_sync(pmask, acc, 1);
                s[jj] = (j0 + c + jj <= row) ? acc * 0.125f : -INFINITY;
            }

            float mc = s[0];
#pragma unroll
            for (int jj = 1; jj < 16; jj++) mc = fmaxf(mc, s[jj]);
            float mn = fmaxf(m, mc);
            float sc = __expf(m - mn);
            l *= sc;
#pragma unroll
            for (int d = 0; d < 32; d++) o[d] *= sc;

#pragma unroll
            for (int jj = 0; jj < 16; jj++) {
                const float p = __expf(s[jj] - mn);
                l += p;
                const float* vr = &Vsh[(c + jj) * KST + dphys];
#pragma unroll
                for (int d = 0; d < 32; d++)
                    o[d] = fmaf(p, vr[d], o[d]);
            }
            m = mn;
        }
        __syncthreads();
    }

    const float inv = 1.0f / l;
    float* op = gatt + rowbase + dlog;
#pragma unroll
    for (int d = 0; d < 32; d += 4) {
        float4 v4;
        v4.x = o[d+0] * inv;
        v4.y = o[d+1] * inv;
        v4.z = o[d+2] * inv;
        v4.w = o[d+3] * inv;
        *(float4*)(op + d) = v4;
    }
}

// ---------------------------------------------------------------------------
// Launch
// ---------------------------------------------------------------------------
extern "C" void kernel_launch(void* const* d_in, const int* in_sizes, int n_in,
                              void* d_out, int out_size)
{
    (void)in_sizes; (void)n_in; (void)out_size;
    const float* x     = (const float*)d_in[0];
    const float* Wk    = (const float*)d_in[1];
    const float* Wq    = (const float*)d_in[2];
    const float* Wv    = (const float*)d_in[3];
    const float* Wproj = (const float*)d_in[4];
    float* out = (float*)d_out;

    float *q_ptr, *k_ptr, *v_ptr, *att_ptr;
    cudaGetSymbolAddress((void**)&q_ptr,   g_q);
    cudaGetSymbolAddress((void**)&k_ptr,   g_k);
    cudaGetSymbolAddress((void**)&v_ptr,   g_v);
    cudaGetSymbolAddress((void**)&att_ptr, g_att);

    const int M = BB * TT;   // 8192
    const int N = EE;        // 1024
    const int K = EE;        // 1024

    dim3 gblk(256);
    dim3 ggrid(N / GBN, M / GBM);  // (8, 64)

    gemm_bf16x3_kernel<<<ggrid, gblk>>>(x, Wk, k_ptr, M, N, K);
    gemm_bf16x3_kernel<<<ggrid, gblk>>>(x, Wq, q_ptr, M, N, K);
    gemm_bf16x3_kernel<<<ggrid, gblk>>>(x, Wv, v_ptr, M, N, K);

    dim3 agrid(TT / AQR, HH, BB);  // (16, 16, 8)
    attn2_kernel<<<agrid, ATH>>>(q_ptr, k_ptr, v_ptr, att_ptr);

    gemm_bf16x3_kernel<<<ggrid, gblk>>>(att_ptr, Wproj, out, M, N, K);
}